// round 15
// baseline (speedup 1.0000x reference)
#include <cuda_runtime.h>
#include <cuda_fp16.h>
#include <cstdint>

#define S_LEN 4096
#define D_MODEL 256
#define NTHREADS 256
#define QPB 32            // 8 warps * 2 queries * 2 sequential groups

__device__ __forceinline__ float ex2f(float a) {
    float r; asm("ex2.approx.f32 %0,%1;" : "=f"(r) : "f"(a)); return r;
}
__device__ __forceinline__ __half2 u2h(uint32_t u) {
    return *reinterpret_cast<__half2*>(&u);
}
// Single-instruction packed exp2 (one MUFU op, 2 halves)
__device__ __forceinline__ __half2 ex2h2(__half2 a) {
    __half2 r;
    asm("ex2.approx.f16x2 %0,%1;"
        : "=r"(*reinterpret_cast<uint32_t*>(&r))
        : "r"(*reinterpret_cast<const uint32_t*>(&a)));
    return r;
}

__global__ __launch_bounds__(NTHREADS) void dwsa_kernel(
    const float2* __restrict__ x,   // [B, S, 2] (size, height)
    const float* __restrict__ Wq,
    const float* __restrict__ Wk,
    const float* __restrict__ Wv,
    float* __restrict__ out)        // [B, S, 256]
{
    __shared__ __half2  nszh[S_LEN / 2];   // -lam2*size f16x2 (8 KB)
    __shared__ __half2  hph [S_LEN / 2];   // height f16x2     (8 KB)
    __shared__ float    red[48];

    const int tid  = threadIdx.x;
    const int lane = tid & 31;
    const int warp = tid >> 5;
    const int blocks_per_batch = S_LEN / QPB;   // 128
    const int b  = blockIdx.x / blocks_per_batch;
    const int q0 = (blockIdx.x % blocks_per_batch) * QPB;

    const float LOG2E = 1.4426950408889634f;
    const float LAM2  = 0.5f * LOG2E;

    // --- Stage batch into packed half2 smem; reductions in f32 ---
    const float2* xb  = x + (size_t)b * S_LEN;
    const float4* xb4 = (const float4*)xb;
    float hmax = -1e30f, hmin = 1e30f, szmax = -1e30f, szmin = 1e30f;
    int zflag = 0;
    for (int i = tid; i < S_LEN / 2; i += NTHREADS) {
        float4 v = xb4[i];                        // {sz0, h0, sz1, h1}
        nszh[i] = __floats2half2_rn(-LAM2 * v.x, -LAM2 * v.z);
        hph [i] = __floats2half2_rn(v.y, v.w);
        hmax = fmaxf(hmax, fmaxf(v.y, v.w));   hmin = fminf(hmin, fminf(v.y, v.w));
        szmax = fmaxf(szmax, fmaxf(v.x, v.z)); szmin = fminf(szmin, fminf(v.x, v.z));
        zflag |= (v.y == 0.f) | (v.w == 0.f);
    }
    float cp = Wq[tid] * Wk[tid];                 // NTHREADS == D_MODEL
    #pragma unroll
    for (int o = 16; o > 0; o >>= 1) {
        hmax  = fmaxf(hmax,  __shfl_xor_sync(0xffffffffu, hmax,  o));
        hmin  = fminf(hmin,  __shfl_xor_sync(0xffffffffu, hmin,  o));
        szmax = fmaxf(szmax, __shfl_xor_sync(0xffffffffu, szmax, o));
        szmin = fminf(szmin, __shfl_xor_sync(0xffffffffu, szmin, o));
        cp   += __shfl_xor_sync(0xffffffffu, cp, o);
    }
    if (lane == 0) {
        red[warp] = hmax; red[8+warp] = hmin; red[16+warp] = szmax;
        red[24+warp] = szmin; red[32+warp] = cp;
    }
    const int anyzero = __syncthreads_or(zflag);
    hmax = red[0]; hmin = red[8]; szmax = red[16]; szmin = red[24];
    float csum = red[32];
    #pragma unroll
    for (int w = 1; w < 8; w++) {
        hmax = fmaxf(hmax, red[w]);       hmin = fminf(hmin, red[8+w]);
        szmax = fmaxf(szmax, red[16+w]);  szmin = fminf(szmin, red[24+w]);
        csum += red[32+w];
    }
    const float c = csum * (1.0f / 16.0f);
    const float wspan = LAM2 * (szmax - szmin);
    const bool fast = (!anyzero) && (wspan <= 13.0f);

    const uint4* nh4 = (const uint4*)nszh;
    const uint4* hp4 = (const uint4*)hph;
    const float4* wv4 = (const float4*)Wv;

    // --- Two sequential groups of (two interleaved queries per warp) ---
    for (int qi2 = 0; qi2 < 2; qi2++) {
        const int sA = q0 + warp + qi2 * 16;
        const int sB = sA + 8;
        const float2 xA = xb[sA], xB = xb[sB];
        const float qszA = LAM2 * xA.x;
        const float qszB = LAM2 * xB.x;
        const float a2A  = c * xA.y * LOG2E;
        const float a2B  = c * xB.y * LOG2E;
        const float nM2A = -fmaxf(a2A * hmax, a2A * hmin);
        const float nM2B = -fmaxf(a2B * hmax, a2B * hmin);

        float zv[2], rv[2];

        if (fast) {
            const __half2 qA2 = __float2half2_rn(qszA);
            const __half2 aA2 = __float2half2_rn(a2A);
            const __half2 mA2 = __float2half2_rn(nM2A);
            const __half2 qB2 = __float2half2_rn(qszB);
            const __half2 aB2 = __float2half2_rn(a2B);
            const __half2 mB2 = __float2half2_rn(nM2B);

            float zA = 0.f, rA = 0.f, zB = 0.f, rB = 0.f;
            for (int g = 0; g < 8; g++) {        // 8 groups x 2 chunks; flush per group
                __half2 z2A = __float2half2_rn(0.f), r2A = __float2half2_rn(0.f);
                __half2 z2B = __float2half2_rn(0.f), r2B = __float2half2_rn(0.f);
                #pragma unroll
                for (int ci = 0; ci < 2; ci++) {
                    const int j = lane + (g * 2 + ci) * 32;
                    uint4 sv = nh4[j];           // 4 half2 = 8 keys (-lam2*sz)
                    uint4 hv = hp4[j];           // 4 half2 = 8 heights
                    #pragma unroll
                    for (int e = 0; e < 4; e++) {
                        uint32_t su = (e == 0) ? sv.x : (e == 1) ? sv.y : (e == 2) ? sv.z : sv.w;
                        uint32_t hu = (e == 0) ? hv.x : (e == 1) ? hv.y : (e == 2) ? hv.z : hv.w;
                        __half2 s2 = u2h(su);
                        __half2 h2 = u2h(hu);
                        {   // query A
                            __half2 d2 = __hadd2(qA2, s2);
                            __half2 t2 = __hfma2(aA2, h2, mA2);
                            __half2 p2 = ex2h2(__hsub2(t2, __habs2(d2)));
                            z2A = __hadd2(z2A, p2);
                            r2A = __hfma2(p2, h2, r2A);
                        }
                        {   // query B
                            __half2 d2 = __hadd2(qB2, s2);
                            __half2 t2 = __hfma2(aB2, h2, mB2);
                            __half2 p2 = ex2h2(__hsub2(t2, __habs2(d2)));
                            z2B = __hadd2(z2B, p2);
                            r2B = __hfma2(p2, h2, r2B);
                        }
                    }
                }
                float2 f;
                f = __half22float2(z2A); zA += f.x + f.y;
                f = __half22float2(r2A); rA += f.x + f.y;
                f = __half22float2(z2B); zB += f.x + f.y;
                f = __half22float2(r2B); rB += f.x + f.y;
            }
            zv[0] = zA; rv[0] = rA; zv[1] = zB; rv[1] = rB;
        } else {
            // Exact f32 fallback (key-masked), reads global x (L1/L2-hot)
            #pragma unroll
            for (int qi = 0; qi < 2; qi++) {
                const float qsz = qi ? qszB : qszA;
                const float a2  = qi ? a2B  : a2A;
                const float nM2 = qi ? nM2B : nM2A;
                float zz = 0.f, rr = 0.f;
                for (int t = lane; t < S_LEN; t += 32) {
                    float2 kx = xb[t];
                    float ht = kx.y;
                    float d  = qsz - LAM2 * kx.x;
                    float p  = ex2f(fmaf(a2, ht, nM2) - fabsf(d));
                    if (ht == 0.f) p = 0.f;
                    zz += p; rr = fmaf(p, ht, rr);
                }
                zv[qi] = zz; rv[qi] = rr;
            }
        }

        #pragma unroll
        for (int qi = 0; qi < 2; qi++) {
            float z = zv[qi], r = rv[qi];
            #pragma unroll
            for (int o = 16; o > 0; o >>= 1) {
                z += __shfl_xor_sync(0xffffffffu, z, o);
                r += __shfl_xor_sync(0xffffffffu, r, o);
            }
            const float val = (z > 0.f) ? __fdividef(r, z) : 0.f;
            const int s = sA + qi * 8;
            float4* o4 = (float4*)(out + ((size_t)b * S_LEN + s) * D_MODEL);
            #pragma unroll
            for (int k = 0; k < 2; k++) {
                float4 w = wv4[lane * 2 + k];
                o4[lane * 2 + k] = make_float4(val * w.x, val * w.y, val * w.z, val * w.w);
            }
        }
    }
}

extern "C" void kernel_launch(void* const* d_in, const int* in_sizes, int n_in,
                              void* d_out, int out_size) {
    const float2* x  = (const float2*)d_in[0];
    const float*  Wq = (const float*)d_in[1];
    const float*  Wk = (const float*)d_in[2];
    const float*  Wv = (const float*)d_in[3];
    float* out = (float*)d_out;

    const int B = in_sizes[0] / (S_LEN * 2);
    const int grid = B * (S_LEN / QPB);     // 1024 blocks -> single wave
    dwsa_kernel<<<grid, NTHREADS>>>(x, Wq, Wk, Wv, out);
}